// round 2
// baseline (speedup 1.0000x reference)
#include <cuda_runtime.h>

#define H_IN  1024
#define D_QKV 64
#define NB    4
#define LSEQ  2048
#define MROWS (NB*LSEQ)   // 8192

// Scratch for projected q/k/v: (N*L, 64) each. __device__ globals (no alloc).
__device__ float g_q[MROWS * D_QKV];
__device__ float g_k[MROWS * D_QKV];
__device__ float g_v[MROWS * D_QKV];

// ============================================================================
// Kernel 1: fused QKV projection.  out = X @ W + b
//   X: (8192, 1024) row-major,  W: (1024, 64),  b: (64)
//   Block tile: 128x64, K-chunk 16, 256 threads, thread tile 8x4.
//   blockIdx.y selects which of the three projections this block computes.
// ============================================================================
#define PBM  128
#define PBK  16
#define PLDA 132   // padded lda for transposed A tile (128 + 4)

__global__ __launch_bounds__(256, 2) void proj_kernel(
    const float* __restrict__ Xq, const float* __restrict__ Xk, const float* __restrict__ Xv,
    const float* __restrict__ Wq, const float* __restrict__ Wk, const float* __restrict__ Wv,
    const float* __restrict__ Bq, const float* __restrict__ Bk, const float* __restrict__ Bv)
{
    const float* X; const float* W; const float* B; float* out;
    switch (blockIdx.y) {
        case 0:  X = Xq; W = Wq; B = Bq; out = g_q; break;
        case 1:  X = Xk; W = Wk; B = Bk; out = g_k; break;
        default: X = Xv; W = Wv; B = Bv; out = g_v; break;
    }

    __shared__ float As[PBK * PLDA];   // A^T tile: As[k][m]
    __shared__ float Bs[PBK * 64];     // B tile:   Bs[k][n]

    const int tid = threadIdx.x;
    const int tx  = tid & 15;          // 0..15 -> n
    const int ty  = tid >> 4;          // 0..15 -> m
    const int m0  = blockIdx.x * PBM;

    const int la_m = tid >> 2;         // 0..63 (two iterations cover 128 rows)
    const int la_k = (tid & 3) * 4;    // 0,4,8,12
    const int lb_k = tid >> 4;         // 0..15
    const int lb_n = (tid & 15) * 4;   // 0..60

    float acc[8][4];
    #pragma unroll
    for (int i = 0; i < 8; i++)
        #pragma unroll
        for (int j = 0; j < 4; j++) acc[i][j] = 0.f;

    for (int kk = 0; kk < H_IN; kk += PBK) {
        // Load & transpose A tile (128 x 16)
        #pragma unroll
        for (int it = 0; it < 2; ++it) {
            const int m = la_m + it * 64;
            float4 v = *(const float4*)&X[(size_t)(m0 + m) * H_IN + kk + la_k];
            As[(la_k + 0) * PLDA + m] = v.x;
            As[(la_k + 1) * PLDA + m] = v.y;
            As[(la_k + 2) * PLDA + m] = v.z;
            As[(la_k + 3) * PLDA + m] = v.w;
        }
        // Load B tile (16 x 64), natural layout
        *(float4*)&Bs[lb_k * 64 + lb_n] =
            *(const float4*)&W[(size_t)(kk + lb_k) * 64 + lb_n];
        __syncthreads();

        #pragma unroll
        for (int k = 0; k < PBK; k++) {
            float a[8], b[4];
            float4 a0 = *(float4*)&As[k * PLDA + ty * 8];
            float4 a1 = *(float4*)&As[k * PLDA + ty * 8 + 4];
            a[0]=a0.x; a[1]=a0.y; a[2]=a0.z; a[3]=a0.w;
            a[4]=a1.x; a[5]=a1.y; a[6]=a1.z; a[7]=a1.w;
            float4 bb = *(float4*)&Bs[k * 64 + tx * 4];
            b[0]=bb.x; b[1]=bb.y; b[2]=bb.z; b[3]=bb.w;
            #pragma unroll
            for (int i = 0; i < 8; i++)
                #pragma unroll
                for (int j = 0; j < 4; j++)
                    acc[i][j] = fmaf(a[i], b[j], acc[i][j]);
        }
        __syncthreads();
    }

    const float4 bias = *(const float4*)&B[tx * 4];
    #pragma unroll
    for (int i = 0; i < 8; i++) {
        const int row = m0 + ty * 8 + i;
        float4 o;
        o.x = acc[i][0] + bias.x;  o.y = acc[i][1] + bias.y;
        o.z = acc[i][2] + bias.z;  o.w = acc[i][3] + bias.w;
        *(float4*)&out[(size_t)row * D_QKV + tx * 4] = o;
    }
}

// ============================================================================
// Kernel 2: flash attention, fp32.
//   Per block: one (batch, 64-row Q tile). Iterate KV in 64-row tiles.
//   SMEM: Q^T [d][r] ld68, K^T/P^T shared buffer ld68, V [c][d] ld68.
//   256 threads, thread tile 4x4 for both 64x64 GEMMs.
// ============================================================================
#define ALD 68   // padded ld (floats); keeps float4 alignment, kills conflicts

__global__ __launch_bounds__(256, 1) void attn_kernel(float* __restrict__ out)
{
    extern __shared__ float sm[];
    float* Qs = sm;                 // Q^T: Qs[d*ALD + r]
    float* KP = sm + 64 * ALD;      // K^T: [d*ALD + c], then P^T: [c*ALD + r]
    float* Vs = sm + 2 * 64 * ALD;  // V:   [c*ALD + d]

    const int tid = threadIdx.x;
    const int tx  = tid & 15;
    const int ty  = tid >> 4;
    const int n   = blockIdx.y;
    const int q0  = blockIdx.x * 64;

    const int lr  = tid >> 2;        // 0..63  (row in 64-row tile)
    const int ld4 = (tid & 3) * 4;   // 0,4,8,12

    const float scale = 0.125f;      // 1/sqrt(64)

    // ---- Load Q tile transposed & pre-scaled ----
    #pragma unroll
    for (int db = 0; db < 4; ++db) {
        const int d4 = ld4 + db * 16;
        float4 v = *(const float4*)&g_q[((size_t)(n * LSEQ + q0 + lr)) * D_QKV + d4];
        Qs[(d4 + 0) * ALD + lr] = v.x * scale;
        Qs[(d4 + 1) * ALD + lr] = v.y * scale;
        Qs[(d4 + 2) * ALD + lr] = v.z * scale;
        Qs[(d4 + 3) * ALD + lr] = v.w * scale;
    }

    float O[4][4];
    float mi[4], li[4];
    #pragma unroll
    for (int i = 0; i < 4; i++) {
        mi[i] = -1e30f; li[i] = 0.f;
        #pragma unroll
        for (int j = 0; j < 4; j++) O[i][j] = 0.f;
    }

    for (int kv0 = 0; kv0 < LSEQ; kv0 += 64) {
        // ---- Load K^T and V tiles ----
        #pragma unroll
        for (int db = 0; db < 4; ++db) {
            const int d4 = ld4 + db * 16;
            const size_t base = ((size_t)(n * LSEQ + kv0 + lr)) * D_QKV + d4;
            float4 kv = *(const float4*)&g_k[base];
            KP[(d4 + 0) * ALD + lr] = kv.x;
            KP[(d4 + 1) * ALD + lr] = kv.y;
            KP[(d4 + 2) * ALD + lr] = kv.z;
            KP[(d4 + 3) * ALD + lr] = kv.w;
            float4 vv = *(const float4*)&g_v[base];
            *(float4*)&Vs[lr * ALD + d4] = vv;
        }
        __syncthreads();

        // ---- S = (Q*scale) @ K^T  (outer product over d) ----
        float S[4][4];
        #pragma unroll
        for (int i = 0; i < 4; i++)
            #pragma unroll
            for (int j = 0; j < 4; j++) S[i][j] = 0.f;

        #pragma unroll 8
        for (int d = 0; d < 64; d++) {
            float4 a = *(float4*)&Qs[d * ALD + ty * 4];
            float4 b = *(float4*)&KP[d * ALD + tx * 4];
            float av[4] = {a.x, a.y, a.z, a.w};
            float bv[4] = {b.x, b.y, b.z, b.w};
            #pragma unroll
            for (int i = 0; i < 4; i++)
                #pragma unroll
                for (int j = 0; j < 4; j++)
                    S[i][j] = fmaf(av[i], bv[j], S[i][j]);
        }
        __syncthreads();   // all reads of K done before P overwrites KP

        // ---- Online softmax (rows r = ty*4 + i; reduce across tx group) ----
        #pragma unroll
        for (int i = 0; i < 4; i++) {
            float mx = fmaxf(fmaxf(S[i][0], S[i][1]), fmaxf(S[i][2], S[i][3]));
            #pragma unroll
            for (int o = 8; o >= 1; o >>= 1)
                mx = fmaxf(mx, __shfl_xor_sync(0xffffffffu, mx, o, 16));
            const float mnew = fmaxf(mi[i], mx);
            const float corr = __expf(mi[i] - mnew);
            mi[i] = mnew;
            float rs = 0.f;
            #pragma unroll
            for (int j = 0; j < 4; j++) {
                S[i][j] = __expf(S[i][j] - mnew);
                rs += S[i][j];
            }
            #pragma unroll
            for (int o = 8; o >= 1; o >>= 1)
                rs += __shfl_xor_sync(0xffffffffu, rs, o, 16);
            li[i] = li[i] * corr + rs;
            #pragma unroll
            for (int j = 0; j < 4; j++) O[i][j] *= corr;
        }

        // ---- Store P^T[c][r] into the K buffer ----
        #pragma unroll
        for (int j = 0; j < 4; j++) {
            float4 p = make_float4(S[0][j], S[1][j], S[2][j], S[3][j]);
            *(float4*)&KP[(tx * 4 + j) * ALD + ty * 4] = p;
        }
        __syncthreads();

        // ---- O += P @ V (outer product over c) ----
        #pragma unroll 8
        for (int c = 0; c < 64; c++) {
            float4 a = *(float4*)&KP[c * ALD + ty * 4];
            float4 b = *(float4*)&Vs[c * ALD + tx * 4];
            float av[4] = {a.x, a.y, a.z, a.w};
            float bv[4] = {b.x, b.y, b.z, b.w};
            #pragma unroll
            for (int i = 0; i < 4; i++)
                #pragma unroll
                for (int j = 0; j < 4; j++)
                    O[i][j] = fmaf(av[i], bv[j], O[i][j]);
        }
        __syncthreads();   // before next tile's loads overwrite KP/Vs
    }

    // ---- Normalize and write out ----
    #pragma unroll
    for (int i = 0; i < 4; i++) {
        const float inv = 1.f / li[i];
        float4 o = make_float4(O[i][0] * inv, O[i][1] * inv,
                               O[i][2] * inv, O[i][3] * inv);
        *(float4*)&out[((size_t)(n * LSEQ + q0 + ty * 4 + i)) * D_QKV + tx * 4] = o;
    }
}

// ============================================================================
// Launch
// ============================================================================
extern "C" void kernel_launch(void* const* d_in, const int* in_sizes, int n_in,
                              void* d_out, int out_size)
{
    const float* q  = (const float*)d_in[0];
    const float* k  = (const float*)d_in[1];
    const float* v  = (const float*)d_in[2];
    const float* Wq = (const float*)d_in[3];
    const float* bq = (const float*)d_in[4];
    const float* Wk = (const float*)d_in[5];
    const float* bk = (const float*)d_in[6];
    const float* Wv = (const float*)d_in[7];
    const float* bv = (const float*)d_in[8];
    float* out = (float*)d_out;

    proj_kernel<<<dim3(MROWS / PBM, 3), 256>>>(q, k, v, Wq, Wk, Wv, bq, bk, bv);

    const int smem = 3 * 64 * ALD * (int)sizeof(float);   // 52224 B
    cudaFuncSetAttribute(attn_kernel,
                         cudaFuncAttributeMaxDynamicSharedMemorySize, smem);
    attn_kernel<<<dim3(LSEQ / 64, NB), 256, smem>>>(out);
}

// round 3
// speedup vs baseline: 2.1039x; 2.1039x over previous
#include <cuda_runtime.h>
#include <cstdint>

#define H_IN  1024
#define D     64
#define NB    4
#define LSEQ  2048
#define MROWS (NB*LSEQ)   // 8192
#define LDB   72          // smem row stride in bf16 elems (64 + 8 pad -> 144B, conflict-free ldmatrix)

// Scratch for projected q/k/v (fp32). __device__ globals (no allocation).
__device__ float g_q[MROWS * D];
__device__ float g_k[MROWS * D];
__device__ float g_v[MROWS * D];

// ---------------------------------------------------------------------------
// helpers
// ---------------------------------------------------------------------------
__device__ __forceinline__ uint32_t s2u(const void* p) {
    uint32_t a;
    asm("{.reg .u64 t; cvta.to.shared.u64 t, %1; cvt.u32.u64 %0, t;}" : "=r"(a) : "l"(p));
    return a;
}

__device__ __forceinline__ void ldsm_x4(uint32_t* r, uint32_t addr) {
    asm volatile("ldmatrix.sync.aligned.m8n8.x4.shared.b16 {%0,%1,%2,%3}, [%4];"
                 : "=r"(r[0]), "=r"(r[1]), "=r"(r[2]), "=r"(r[3]) : "r"(addr));
}
__device__ __forceinline__ void ldsm_x2(uint32_t* r, uint32_t addr) {
    asm volatile("ldmatrix.sync.aligned.m8n8.x2.shared.b16 {%0,%1}, [%2];"
                 : "=r"(r[0]), "=r"(r[1]) : "r"(addr));
}
__device__ __forceinline__ void ldsm_x2_t(uint32_t* r, uint32_t addr) {
    asm volatile("ldmatrix.sync.aligned.m8n8.x2.trans.shared.b16 {%0,%1}, [%2];"
                 : "=r"(r[0]), "=r"(r[1]) : "r"(addr));
}

__device__ __forceinline__ void mma16816(float* c, const uint32_t* a, const uint32_t* b) {
    asm volatile("mma.sync.aligned.m16n8k16.row.col.f32.bf16.bf16.f32 "
                 "{%0,%1,%2,%3}, {%4,%5,%6,%7}, {%8,%9}, {%0,%1,%2,%3};"
                 : "+f"(c[0]), "+f"(c[1]), "+f"(c[2]), "+f"(c[3])
                 : "r"(a[0]), "r"(a[1]), "r"(a[2]), "r"(a[3]), "r"(b[0]), "r"(b[1]));
}

// Truncate-split a float4 into bf16x2 hi words + bf16 lo words (rounded).
// x = hi + lo + O(2^-17 * x).
__device__ __forceinline__ void split4(float4 v, uint2& hi, uint2& lo) {
    uint32_t ux = __float_as_uint(v.x), uy = __float_as_uint(v.y);
    uint32_t uz = __float_as_uint(v.z), uw = __float_as_uint(v.w);
    asm("prmt.b32 %0, %1, %2, 0x7632;" : "=r"(hi.x) : "r"(ux), "r"(uy));
    asm("prmt.b32 %0, %1, %2, 0x7632;" : "=r"(hi.y) : "r"(uz), "r"(uw));
    float rx = v.x - __uint_as_float(ux & 0xFFFF0000u);
    float ry = v.y - __uint_as_float(uy & 0xFFFF0000u);
    float rz = v.z - __uint_as_float(uz & 0xFFFF0000u);
    float rw = v.w - __uint_as_float(uw & 0xFFFF0000u);
    asm("cvt.rn.bf16x2.f32 %0, %1, %2;" : "=r"(lo.x) : "f"(ry), "f"(rx));
    asm("cvt.rn.bf16x2.f32 %0, %1, %2;" : "=r"(lo.y) : "f"(rw), "f"(rz));
}

__device__ __forceinline__ uint32_t pack_hi(float a, float b) {
    uint32_t r;
    asm("prmt.b32 %0, %1, %2, 0x7632;" : "=r"(r)
        : "r"(__float_as_uint(a)), "r"(__float_as_uint(b)));
    return r;
}
__device__ __forceinline__ uint32_t pack_lo(float a, float b) {
    float ra = a - __uint_as_float(__float_as_uint(a) & 0xFFFF0000u);
    float rb = b - __uint_as_float(__float_as_uint(b) & 0xFFFF0000u);
    uint32_t r;
    asm("cvt.rn.bf16x2.f32 %0, %1, %2;" : "=r"(r) : "f"(rb), "f"(ra));
    return r;
}

// ---------------------------------------------------------------------------
// Kernel 1: QKV projection via mma.sync. out = X @ W + b   (8192x1024 . 1024x64)
// 256 threads (8 warps). CTA tile M=128,N=64, K chunk 64. Warp: 16 rows x 64 cols.
// ---------------------------------------------------------------------------
__global__ __launch_bounds__(256, 1) void proj_mma(
    const float* __restrict__ Xq, const float* __restrict__ Xk, const float* __restrict__ Xv,
    const float* __restrict__ Wq, const float* __restrict__ Wk, const float* __restrict__ Wv,
    const float* __restrict__ Bq, const float* __restrict__ Bk, const float* __restrict__ Bv)
{
    const float* X; const float* W; const float* Bias; float* out;
    switch (blockIdx.y) {
        case 0:  X = Xq; W = Wq; Bias = Bq; out = g_q; break;
        case 1:  X = Xk; W = Wk; Bias = Bk; out = g_k; break;
        default: X = Xv; W = Wv; Bias = Bv; out = g_v; break;
    }

    extern __shared__ uint16_t sp[];
    uint16_t* Ah = sp;                 // [128][LDB]
    uint16_t* Al = Ah + 128 * LDB;
    uint16_t* Bh = Al + 128 * LDB;     // [64][LDB]
    uint16_t* Bl = Bh + 64 * LDB;

    const int tid  = threadIdx.x;
    const int lane = tid & 31;
    const int w    = tid >> 5;
    const int m0   = blockIdx.x * 128;

    float acc[8][4];
    #pragma unroll
    for (int nt = 0; nt < 8; nt++)
        #pragma unroll
        for (int j = 0; j < 4; j++) acc[nt][j] = 0.f;

    for (int kk = 0; kk < H_IN; kk += 64) {
        // X chunk: 128 x 64 f32 -> split into Ah/Al
        #pragma unroll
        for (int i = 0; i < 8; i++) {
            const int idx = tid + i * 256;
            const int row = idx >> 4, f4 = idx & 15;
            float4 v = *(const float4*)&X[(size_t)(m0 + row) * H_IN + kk + f4 * 4];
            uint2 hi, lo; split4(v, hi, lo);
            *(uint2*)&Ah[row * LDB + f4 * 4] = hi;
            *(uint2*)&Al[row * LDB + f4 * 4] = lo;
        }
        // W chunk: 64 x 64 f32 -> Bh/Bl
        #pragma unroll
        for (int i = 0; i < 4; i++) {
            const int idx = tid + i * 256;
            const int row = idx >> 4, f4 = idx & 15;
            float4 v = *(const float4*)&W[(size_t)(kk + row) * D + f4 * 4];
            uint2 hi, lo; split4(v, hi, lo);
            *(uint2*)&Bh[row * LDB + f4 * 4] = hi;
            *(uint2*)&Bl[row * LDB + f4 * 4] = lo;
        }
        __syncthreads();

        uint32_t ah[4], al[4], bh[2], bl[2];
        #pragma unroll
        for (int kt = 0; kt < 4; kt++) {
            const int aoff = (w * 16 + (lane & 15)) * LDB + kt * 16 + (lane >> 4) * 8;
            ldsm_x4(ah, s2u(&Ah[aoff]));
            ldsm_x4(al, s2u(&Al[aoff]));
            #pragma unroll
            for (int nt = 0; nt < 8; nt++) {
                const int boff = (kt * 16 + (lane & 15)) * LDB + nt * 8;
                ldsm_x2_t(bh, s2u(&Bh[boff]));
                ldsm_x2_t(bl, s2u(&Bl[boff]));
                mma16816(acc[nt], ah, bh);
                mma16816(acc[nt], ah, bl);
                mma16816(acc[nt], al, bh);
            }
        }
        __syncthreads();
    }

    // epilogue: add bias, write fp32
    const int r0 = m0 + w * 16 + (lane >> 2);
    #pragma unroll
    for (int nt = 0; nt < 8; nt++) {
        const int c = nt * 8 + (lane & 3) * 2;
        const float b0 = Bias[c], b1 = Bias[c + 1];
        float2 o0 = make_float2(acc[nt][0] + b0, acc[nt][1] + b1);
        float2 o1 = make_float2(acc[nt][2] + b0, acc[nt][3] + b1);
        *(float2*)&out[(size_t)r0 * D + c]       = o0;
        *(float2*)&out[(size_t)(r0 + 8) * D + c] = o1;
    }
}

// ---------------------------------------------------------------------------
// Kernel 2: flash attention via mma.sync.
// 128 threads (4 warps). CTA: one (batch, 64-row Q tile). KV tiles of 64.
// Warp: 16 Q rows. S warp tile 16x64, O warp tile 16x64.
// ---------------------------------------------------------------------------
__global__ __launch_bounds__(128, 1) void attn_mma(float* __restrict__ out)
{
    extern __shared__ uint16_t sa[];
    uint16_t* Qh = sa;              // [64][LDB]
    uint16_t* Ql = Qh + 64 * LDB;
    uint16_t* Kh = Ql + 64 * LDB;
    uint16_t* Kl = Kh + 64 * LDB;
    uint16_t* Vh = Kl + 64 * LDB;
    uint16_t* Vl = Vh + 64 * LDB;

    const int tid  = threadIdx.x;
    const int lane = tid & 31;
    const int w    = tid >> 5;
    const int n    = blockIdx.y;
    const int q0   = blockIdx.x * 64;

    // ---- load Q tile, pre-scaled by 1/sqrt(64) ----
    #pragma unroll
    for (int i = 0; i < 8; i++) {
        const int idx = tid + i * 128;
        const int row = idx >> 4, f4 = idx & 15;
        float4 v = *(const float4*)&g_q[((size_t)(n * LSEQ + q0 + row)) * D + f4 * 4];
        v.x *= 0.125f; v.y *= 0.125f; v.z *= 0.125f; v.w *= 0.125f;
        uint2 hi, lo; split4(v, hi, lo);
        *(uint2*)&Qh[row * LDB + f4 * 4] = hi;
        *(uint2*)&Ql[row * LDB + f4 * 4] = lo;
    }
    __syncthreads();

    // ---- preload Q fragments (constant across KV loop) ----
    uint32_t qh[4][4], ql[4][4];
    #pragma unroll
    for (int kt = 0; kt < 4; kt++) {
        const int aoff = (w * 16 + (lane & 15)) * LDB + kt * 16 + (lane >> 4) * 8;
        ldsm_x4(qh[kt], s2u(&Qh[aoff]));
        ldsm_x4(ql[kt], s2u(&Ql[aoff]));
    }

    float o[8][4];
    #pragma unroll
    for (int nt = 0; nt < 8; nt++)
        #pragma unroll
        for (int j = 0; j < 4; j++) o[nt][j] = 0.f;
    float m0v = -1e30f, m1v = -1e30f, l0 = 0.f, l1 = 0.f;

    for (int kv0 = 0; kv0 < LSEQ; kv0 += 64) {
        __syncthreads();   // previous tile's V reads complete before overwrite
        #pragma unroll
        for (int i = 0; i < 8; i++) {
            const int idx = tid + i * 128;
            const int row = idx >> 4, f4 = idx & 15;
            const size_t base = ((size_t)(n * LSEQ + kv0 + row)) * D + f4 * 4;
            uint2 hi, lo;
            float4 kv = *(const float4*)&g_k[base];
            split4(kv, hi, lo);
            *(uint2*)&Kh[row * LDB + f4 * 4] = hi;
            *(uint2*)&Kl[row * LDB + f4 * 4] = lo;
            float4 vv = *(const float4*)&g_v[base];
            split4(vv, hi, lo);
            *(uint2*)&Vh[row * LDB + f4 * 4] = hi;
            *(uint2*)&Vl[row * LDB + f4 * 4] = lo;
        }
        __syncthreads();

        // ---- S = Q @ K^T ----
        float s[8][4];
        #pragma unroll
        for (int nt = 0; nt < 8; nt++)
            #pragma unroll
            for (int j = 0; j < 4; j++) s[nt][j] = 0.f;

        uint32_t bh[2], bl[2];
        #pragma unroll
        for (int kt = 0; kt < 4; kt++) {
            #pragma unroll
            for (int nt = 0; nt < 8; nt++) {
                const int boff = (nt * 8 + (lane & 7)) * LDB + kt * 16 + ((lane >> 3) & 1) * 8;
                ldsm_x2(bh, s2u(&Kh[boff]));
                ldsm_x2(bl, s2u(&Kl[boff]));
                mma16816(s[nt], qh[kt], bh);
                mma16816(s[nt], qh[kt], bl);
                mma16816(s[nt], ql[kt], bh);
            }
        }

        // ---- online softmax (rows: r = lane>>2 in regs {0,1}; r+8 in {2,3}) ----
        float mx0 = -1e30f, mx1 = -1e30f;
        #pragma unroll
        for (int nt = 0; nt < 8; nt++) {
            mx0 = fmaxf(mx0, fmaxf(s[nt][0], s[nt][1]));
            mx1 = fmaxf(mx1, fmaxf(s[nt][2], s[nt][3]));
        }
        mx0 = fmaxf(mx0, __shfl_xor_sync(0xffffffffu, mx0, 1));
        mx0 = fmaxf(mx0, __shfl_xor_sync(0xffffffffu, mx0, 2));
        mx1 = fmaxf(mx1, __shfl_xor_sync(0xffffffffu, mx1, 1));
        mx1 = fmaxf(mx1, __shfl_xor_sync(0xffffffffu, mx1, 2));
        const float mn0 = fmaxf(m0v, mx0), mn1 = fmaxf(m1v, mx1);
        const float corr0 = __expf(m0v - mn0), corr1 = __expf(m1v - mn1);
        m0v = mn0; m1v = mn1;
        float rs0 = 0.f, rs1 = 0.f;
        #pragma unroll
        for (int nt = 0; nt < 8; nt++) {
            s[nt][0] = __expf(s[nt][0] - mn0); rs0 += s[nt][0];
            s[nt][1] = __expf(s[nt][1] - mn0); rs0 += s[nt][1];
            s[nt][2] = __expf(s[nt][2] - mn1); rs1 += s[nt][2];
            s[nt][3] = __expf(s[nt][3] - mn1); rs1 += s[nt][3];
        }
        rs0 += __shfl_xor_sync(0xffffffffu, rs0, 1);
        rs0 += __shfl_xor_sync(0xffffffffu, rs0, 2);
        rs1 += __shfl_xor_sync(0xffffffffu, rs1, 1);
        rs1 += __shfl_xor_sync(0xffffffffu, rs1, 2);
        l0 = l0 * corr0 + rs0;
        l1 = l1 * corr1 + rs1;
        #pragma unroll
        for (int nt = 0; nt < 8; nt++) {
            o[nt][0] *= corr0; o[nt][1] *= corr0;
            o[nt][2] *= corr1; o[nt][3] *= corr1;
        }

        // ---- O += P @ V  (P fragments packed from registers) ----
        #pragma unroll
        for (int kt = 0; kt < 4; kt++) {
            uint32_t ph[4], pl[4];
            ph[0] = pack_hi(s[2*kt][0],   s[2*kt][1]);
            ph[1] = pack_hi(s[2*kt][2],   s[2*kt][3]);
            ph[2] = pack_hi(s[2*kt+1][0], s[2*kt+1][1]);
            ph[3] = pack_hi(s[2*kt+1][2], s[2*kt+1][3]);
            pl[0] = pack_lo(s[2*kt][0],   s[2*kt][1]);
            pl[1] = pack_lo(s[2*kt][2],   s[2*kt][3]);
            pl[2] = pack_lo(s[2*kt+1][0], s[2*kt+1][1]);
            pl[3] = pack_lo(s[2*kt+1][2], s[2*kt+1][3]);
            #pragma unroll
            for (int nt = 0; nt < 8; nt++) {
                const int boff = (kt * 16 + (lane & 15)) * LDB + nt * 8;
                ldsm_x2_t(bh, s2u(&Vh[boff]));
                ldsm_x2_t(bl, s2u(&Vl[boff]));
                mma16816(o[nt], ph, bh);
                mma16816(o[nt], ph, bl);
                mma16816(o[nt], pl, bh);
            }
        }
    }

    // ---- normalize + write ----
    const float inv0 = 1.f / l0, inv1 = 1.f / l1;
    const int r0 = q0 + w * 16 + (lane >> 2);
    #pragma unroll
    for (int nt = 0; nt < 8; nt++) {
        const int c = nt * 8 + (lane & 3) * 2;
        float2 o0 = make_float2(o[nt][0] * inv0, o[nt][1] * inv0);
        float2 o1 = make_float2(o[nt][2] * inv1, o[nt][3] * inv1);
        *(float2*)&out[((size_t)(n * LSEQ + r0)) * D + c]     = o0;
        *(float2*)&out[((size_t)(n * LSEQ + r0 + 8)) * D + c] = o1;
    }
}

// ---------------------------------------------------------------------------
// Launch
// ---------------------------------------------------------------------------
extern "C" void kernel_launch(void* const* d_in, const int* in_sizes, int n_in,
                              void* d_out, int out_size)
{
    const float* q  = (const float*)d_in[0];
    const float* k  = (const float*)d_in[1];
    const float* v  = (const float*)d_in[2];
    const float* Wq = (const float*)d_in[3];
    const float* bq = (const float*)d_in[4];
    const float* Wk = (const float*)d_in[5];
    const float* bk = (const float*)d_in[6];
    const float* Wv = (const float*)d_in[7];
    const float* bv = (const float*)d_in[8];
    float* out = (float*)d_out;

    const int smem_proj = (128 + 128 + 64 + 64) * LDB * 2;   // 55296 B
    const int smem_attn = 6 * 64 * LDB * 2;                  // 55296 B
    cudaFuncSetAttribute(proj_mma, cudaFuncAttributeMaxDynamicSharedMemorySize, smem_proj);
    cudaFuncSetAttribute(attn_mma, cudaFuncAttributeMaxDynamicSharedMemorySize, smem_attn);

    proj_mma<<<dim3(MROWS / 128, 3), 256, smem_proj>>>(q, k, v, Wq, Wk, Wv, bq, bk, bv);
    attn_mma<<<dim3(LSEQ / 64, NB), 128, smem_attn>>>(out);
}

// round 4
// speedup vs baseline: 2.6302x; 1.2501x over previous
#include <cuda_runtime.h>
#include <cstdint>

#define H_IN  1024
#define D     64
#define NB    4
#define LSEQ  2048
#define MROWS (NB*LSEQ)     // 8192
#define LDB   72            // smem row stride (bf16 elems): 144B, conflict-free ldmatrix
#define NTILES (LSEQ/64)    // 32

// Pre-split projected tensors (hi/lo bf16). Q is pre-scaled by 1/8.
__device__ uint16_t g_qh[MROWS * D];
__device__ uint16_t g_ql[MROWS * D];
__device__ uint16_t g_kh[MROWS * D];
__device__ uint16_t g_kl[MROWS * D];
__device__ uint16_t g_vh[MROWS * D];
__device__ uint16_t g_vl[MROWS * D];

// ---------------------------------------------------------------------------
// helpers
// ---------------------------------------------------------------------------
__device__ __forceinline__ uint32_t s2u(const void* p) {
    uint32_t a;
    asm("{.reg .u64 t; cvta.to.shared.u64 t, %1; cvt.u32.u64 %0, t;}" : "=r"(a) : "l"(p));
    return a;
}
__device__ __forceinline__ void ldsm_x4(uint32_t* r, uint32_t addr) {
    asm volatile("ldmatrix.sync.aligned.m8n8.x4.shared.b16 {%0,%1,%2,%3}, [%4];"
                 : "=r"(r[0]), "=r"(r[1]), "=r"(r[2]), "=r"(r[3]) : "r"(addr));
}
__device__ __forceinline__ void ldsm_x4_t(uint32_t* r, uint32_t addr) {
    asm volatile("ldmatrix.sync.aligned.m8n8.x4.trans.shared.b16 {%0,%1,%2,%3}, [%4];"
                 : "=r"(r[0]), "=r"(r[1]), "=r"(r[2]), "=r"(r[3]) : "r"(addr));
}
__device__ __forceinline__ void mma16816(float* c, const uint32_t* a, const uint32_t* b) {
    asm volatile("mma.sync.aligned.m16n8k16.row.col.f32.bf16.bf16.f32 "
                 "{%0,%1,%2,%3}, {%4,%5,%6,%7}, {%8,%9}, {%0,%1,%2,%3};"
                 : "+f"(c[0]), "+f"(c[1]), "+f"(c[2]), "+f"(c[3])
                 : "r"(a[0]), "r"(a[1]), "r"(a[2]), "r"(a[3]), "r"(b[0]), "r"(b[1]));
}
// Truncate-split float4 -> bf16x2 hi words + rounded bf16 lo words.
__device__ __forceinline__ void split4(float4 v, uint2& hi, uint2& lo) {
    uint32_t ux = __float_as_uint(v.x), uy = __float_as_uint(v.y);
    uint32_t uz = __float_as_uint(v.z), uw = __float_as_uint(v.w);
    asm("prmt.b32 %0, %1, %2, 0x7632;" : "=r"(hi.x) : "r"(ux), "r"(uy));
    asm("prmt.b32 %0, %1, %2, 0x7632;" : "=r"(hi.y) : "r"(uz), "r"(uw));
    float rx = v.x - __uint_as_float(ux & 0xFFFF0000u);
    float ry = v.y - __uint_as_float(uy & 0xFFFF0000u);
    float rz = v.z - __uint_as_float(uz & 0xFFFF0000u);
    float rw = v.w - __uint_as_float(uw & 0xFFFF0000u);
    asm("cvt.rn.bf16x2.f32 %0, %1, %2;" : "=r"(lo.x) : "f"(ry), "f"(rx));
    asm("cvt.rn.bf16x2.f32 %0, %1, %2;" : "=r"(lo.y) : "f"(rw), "f"(rz));
}
__device__ __forceinline__ uint32_t pack_hi(float a, float b) {
    uint32_t r;
    asm("prmt.b32 %0, %1, %2, 0x7632;" : "=r"(r)
        : "r"(__float_as_uint(a)), "r"(__float_as_uint(b)));
    return r;
}
__device__ __forceinline__ uint32_t pack_lo(float a, float b) {
    float ra = a - __uint_as_float(__float_as_uint(a) & 0xFFFF0000u);
    float rb = b - __uint_as_float(__float_as_uint(b) & 0xFFFF0000u);
    uint32_t r;
    asm("cvt.rn.bf16x2.f32 %0, %1, %2;" : "=r"(r) : "f"(rb), "f"(ra));
    return r;
}
template <int N> __device__ __forceinline__ void cp_wait() {
    asm volatile("cp.async.wait_group %0;" :: "n"(N) : "memory");
}
__device__ __forceinline__ void cp_commit() {
    asm volatile("cp.async.commit_group;" ::: "memory");
}
__device__ __forceinline__ void cp16(uint32_t saddr, const void* gaddr) {
    asm volatile("cp.async.cg.shared.global [%0], [%1], 16;"
                 :: "r"(saddr), "l"(gaddr) : "memory");
}

// ---------------------------------------------------------------------------
// Kernel 1: QKV projection. X(8192x1024) @ W(1024x64) + b -> split hi/lo bf16.
// 128 threads (4 warps), CTA tile M=64, K-chunk 64; grid (128, 3).
// ---------------------------------------------------------------------------
__global__ __launch_bounds__(128) void proj_mma(
    const float* __restrict__ Xq, const float* __restrict__ Xk, const float* __restrict__ Xv,
    const float* __restrict__ Wq, const float* __restrict__ Wk, const float* __restrict__ Wv,
    const float* __restrict__ Bq, const float* __restrict__ Bk, const float* __restrict__ Bv)
{
    const float* X; const float* W; const float* Bias;
    uint16_t* outH; uint16_t* outL; float scale;
    switch (blockIdx.y) {
        case 0:  X = Xq; W = Wq; Bias = Bq; outH = g_qh; outL = g_ql; scale = 0.125f; break;
        case 1:  X = Xk; W = Wk; Bias = Bk; outH = g_kh; outL = g_kl; scale = 1.0f;   break;
        default: X = Xv; W = Wv; Bias = Bv; outH = g_vh; outL = g_vl; scale = 1.0f;   break;
    }

    extern __shared__ uint16_t sp[];
    uint16_t* Ah = sp;                 // [64][LDB]
    uint16_t* Al = Ah + 64 * LDB;
    uint16_t* Bh = Al + 64 * LDB;
    uint16_t* Bl = Bh + 64 * LDB;

    const int tid  = threadIdx.x;
    const int lane = tid & 31;
    const int w    = tid >> 5;
    const int m0   = blockIdx.x * 64;
    const int g    = lane >> 3, l8 = lane & 7;

    float acc[8][4];
    #pragma unroll
    for (int nt = 0; nt < 8; nt++)
        #pragma unroll
        for (int j = 0; j < 4; j++) acc[nt][j] = 0.f;

    // prefetch X chunk 0
    float4 xv[8];
    #pragma unroll
    for (int i = 0; i < 8; i++) {
        const int idx = tid + i * 128;
        xv[i] = *(const float4*)&X[(size_t)(m0 + (idx >> 4)) * H_IN + (idx & 15) * 4];
    }

    for (int kk = 0; kk < H_IN; kk += 64) {
        // load W chunk
        float4 wv[8];
        #pragma unroll
        for (int i = 0; i < 8; i++) {
            const int idx = tid + i * 128;
            wv[i] = *(const float4*)&W[(size_t)(kk + (idx >> 4)) * D + (idx & 15) * 4];
        }
        // store X chunk (split)
        #pragma unroll
        for (int i = 0; i < 8; i++) {
            const int idx = tid + i * 128;
            const int row = idx >> 4, f4 = idx & 15;
            uint2 hi, lo; split4(xv[i], hi, lo);
            *(uint2*)&Ah[row * LDB + f4 * 4] = hi;
            *(uint2*)&Al[row * LDB + f4 * 4] = lo;
        }
        // store W chunk (split)
        #pragma unroll
        for (int i = 0; i < 8; i++) {
            const int idx = tid + i * 128;
            const int row = idx >> 4, f4 = idx & 15;
            uint2 hi, lo; split4(wv[i], hi, lo);
            *(uint2*)&Bh[row * LDB + f4 * 4] = hi;
            *(uint2*)&Bl[row * LDB + f4 * 4] = lo;
        }
        __syncthreads();

        // prefetch next X chunk (hidden under mma)
        if (kk + 64 < H_IN) {
            #pragma unroll
            for (int i = 0; i < 8; i++) {
                const int idx = tid + i * 128;
                xv[i] = *(const float4*)&X[(size_t)(m0 + (idx >> 4)) * H_IN + kk + 64 + (idx & 15) * 4];
            }
        }

        uint32_t ah[4], al[4], bb[4], bl[4];
        #pragma unroll
        for (int kt = 0; kt < 4; kt++) {
            const int aoff = (w * 16 + (lane & 15)) * LDB + kt * 16 + (lane >> 4) * 8;
            ldsm_x4(ah, s2u(&Ah[aoff]));
            ldsm_x4(al, s2u(&Al[aoff]));
            #pragma unroll
            for (int p = 0; p < 4; p++) {   // nt pairs (2p, 2p+1)
                const int row = kt * 16 + (g & 1) * 8 + l8;
                const int col = (2 * p + (g >> 1)) * 8;
                ldsm_x4_t(bb, s2u(&Bh[row * LDB + col]));
                ldsm_x4_t(bl, s2u(&Bl[row * LDB + col]));
                mma16816(acc[2*p],   ah, bb);     mma16816(acc[2*p],   ah, bl);
                mma16816(acc[2*p],   al, bb);
                mma16816(acc[2*p+1], ah, bb + 2); mma16816(acc[2*p+1], ah, bl + 2);
                mma16816(acc[2*p+1], al, bb + 2);
            }
        }
        __syncthreads();
    }

    // epilogue: bias, scale, split, store
    const int r0 = m0 + w * 16 + (lane >> 2);
    #pragma unroll
    for (int nt = 0; nt < 8; nt++) {
        const int c = nt * 8 + (lane & 3) * 2;
        const float2 b2 = *(const float2*)&Bias[c];
        const float y0 = (acc[nt][0] + b2.x) * scale;
        const float y1 = (acc[nt][1] + b2.y) * scale;
        const float y2 = (acc[nt][2] + b2.x) * scale;
        const float y3 = (acc[nt][3] + b2.y) * scale;
        *(uint32_t*)&outH[(size_t)r0 * D + c]       = pack_hi(y0, y1);
        *(uint32_t*)&outL[(size_t)r0 * D + c]       = pack_lo(y0, y1);
        *(uint32_t*)&outH[(size_t)(r0 + 8) * D + c] = pack_hi(y2, y3);
        *(uint32_t*)&outL[(size_t)(r0 + 8) * D + c] = pack_lo(y2, y3);
    }
}

// ---------------------------------------------------------------------------
// Kernel 2: flash attention. 256 threads (8 warps), 64-row Q tile.
// Warp = (row-group rg = w&3: 16 rows) x (KV half kh = w>>2: 32 cols).
// 2-stage cp.async pipeline over KV tiles of pre-split K/V.
// ---------------------------------------------------------------------------
__device__ __forceinline__ void issue_kv(uint16_t* ST, int st, int n, int t, int tid)
{
    const int tile = tid >> 6;          // 0:Kh 1:Kl 2:Vh 3:Vl
    const int cc0  = tid & 63;
    const uint16_t* gp = (tile == 0) ? g_kh : (tile == 1) ? g_kl
                        : (tile == 2) ? g_vh : g_vl;
    uint16_t* sp = ST + (size_t)(st * 4 + tile) * 64 * LDB;
    const size_t gbase = ((size_t)n * LSEQ + (size_t)t * 64) * D;
    #pragma unroll
    for (int j = 0; j < 8; j++) {
        const int cc  = cc0 + j * 64;
        const int row = cc >> 3, col = (cc & 7) * 8;
        cp16(s2u(&sp[row * LDB + col]), &gp[gbase + (size_t)row * D + col]);
    }
    cp_commit();
}

__global__ __launch_bounds__(256) void attn_mma(float* __restrict__ out)
{
    extern __shared__ uint16_t sa[];
    uint16_t* Qh = sa;
    uint16_t* Ql = Qh + 64 * LDB;
    uint16_t* ST = Ql + 64 * LDB;                 // 8 KV tiles (2 stages x {Kh,Kl,Vh,Vl})
    float* redA = (float*)(ST + 8 * 64 * LDB);    // [2][64]
    float* redB = redA + 128;                     // [2][64]

    const int tid  = threadIdx.x;
    const int lane = tid & 31;
    const int w    = tid >> 5;
    const int rg   = w & 3;        // 16-row group
    const int kh   = w >> 2;       // KV half
    const int g    = lane >> 3, l8 = lane & 7;
    const int n    = blockIdx.y;
    const int q0   = blockIdx.x * 64;

    // start pipeline for tile 0 first
    issue_kv(ST, 0, n, 0, tid);

    // load Q hi/lo tiles (already pre-scaled)
    #pragma unroll
    for (int j = 0; j < 2; j++) {
        const uint16_t* gp = j ? g_ql : g_qh;
        uint16_t* spq = j ? Ql : Qh;
        #pragma unroll
        for (int i = 0; i < 2; i++) {
            const int cc = tid + i * 256;
            const int row = cc >> 3, col = (cc & 7) * 8;
            *(uint4*)&spq[row * LDB + col] =
                *(const uint4*)&gp[((size_t)(n * LSEQ + q0 + row)) * D + col];
        }
    }
    __syncthreads();

    uint32_t qh[4][4], ql[4][4];
    #pragma unroll
    for (int kt = 0; kt < 4; kt++) {
        const int aoff = (rg * 16 + (lane & 15)) * LDB + kt * 16 + (lane >> 4) * 8;
        ldsm_x4(qh[kt], s2u(&Qh[aoff]));
        ldsm_x4(ql[kt], s2u(&Ql[aoff]));
    }

    float o[8][4];
    #pragma unroll
    for (int nt = 0; nt < 8; nt++)
        #pragma unroll
        for (int j = 0; j < 4; j++) o[nt][j] = 0.f;
    float m0v = -1e30f, m1v = -1e30f, l0 = 0.f, l1 = 0.f;

    const int rrow = rg * 16 + (lane >> 2);   // global-in-tile row this lane owns (and +8)

    for (int t = 0; t < NTILES; t++) {
        const int st = t & 1;
        if (t + 1 < NTILES) { issue_kv(ST, (t + 1) & 1, n, t + 1, tid); cp_wait<1>(); }
        else                { cp_wait<0>(); }
        __syncthreads();   // B1: stage st ready

        uint16_t* sKh = ST + (size_t)(st * 4 + 0) * 64 * LDB;
        uint16_t* sKl = ST + (size_t)(st * 4 + 1) * 64 * LDB;
        uint16_t* sVh = ST + (size_t)(st * 4 + 2) * 64 * LDB;
        uint16_t* sVl = ST + (size_t)(st * 4 + 3) * 64 * LDB;

        // ---- S = Q @ K^T  (warp: 16 rows x 32 cols) ----
        float s[4][4];
        #pragma unroll
        for (int nt = 0; nt < 4; nt++)
            #pragma unroll
            for (int j = 0; j < 4; j++) s[nt][j] = 0.f;

        #pragma unroll
        for (int kt = 0; kt < 4; kt++) {
            uint32_t kb[4], kl_[4];
            #pragma unroll
            for (int p = 0; p < 2; p++) {
                const int row  = kh * 32 + p * 16 + (g >> 1) * 8 + l8;
                const int koff = kt * 16 + (g & 1) * 8;
                ldsm_x4(kb,  s2u(&sKh[row * LDB + koff]));
                ldsm_x4(kl_, s2u(&sKl[row * LDB + koff]));
                mma16816(s[2*p],   qh[kt], kb);     mma16816(s[2*p],   qh[kt], kl_);
                mma16816(s[2*p],   ql[kt], kb);
                mma16816(s[2*p+1], qh[kt], kb + 2); mma16816(s[2*p+1], qh[kt], kl_ + 2);
                mma16816(s[2*p+1], ql[kt], kb + 2);
            }
        }

        // ---- online softmax across the warp pair ----
        float mx0 = -1e30f, mx1 = -1e30f;
        #pragma unroll
        for (int nt = 0; nt < 4; nt++) {
            mx0 = fmaxf(mx0, fmaxf(s[nt][0], s[nt][1]));
            mx1 = fmaxf(mx1, fmaxf(s[nt][2], s[nt][3]));
        }
        mx0 = fmaxf(mx0, __shfl_xor_sync(0xffffffffu, mx0, 1));
        mx0 = fmaxf(mx0, __shfl_xor_sync(0xffffffffu, mx0, 2));
        mx1 = fmaxf(mx1, __shfl_xor_sync(0xffffffffu, mx1, 1));
        mx1 = fmaxf(mx1, __shfl_xor_sync(0xffffffffu, mx1, 2));
        if ((lane & 3) == 0) {
            redA[kh * 64 + rrow]     = mx0;
            redA[kh * 64 + rrow + 8] = mx1;
        }
        __syncthreads();   // B2
        mx0 = fmaxf(mx0, redA[(kh ^ 1) * 64 + rrow]);
        mx1 = fmaxf(mx1, redA[(kh ^ 1) * 64 + rrow + 8]);
        const float mn0 = fmaxf(m0v, mx0), mn1 = fmaxf(m1v, mx1);
        const float corr0 = __expf(m0v - mn0), corr1 = __expf(m1v - mn1);
        m0v = mn0; m1v = mn1;
        float rs0 = 0.f, rs1 = 0.f;
        #pragma unroll
        for (int nt = 0; nt < 4; nt++) {
            s[nt][0] = __expf(s[nt][0] - mn0); rs0 += s[nt][0];
            s[nt][1] = __expf(s[nt][1] - mn0); rs0 += s[nt][1];
            s[nt][2] = __expf(s[nt][2] - mn1); rs1 += s[nt][2];
            s[nt][3] = __expf(s[nt][3] - mn1); rs1 += s[nt][3];
        }
        rs0 += __shfl_xor_sync(0xffffffffu, rs0, 1);
        rs0 += __shfl_xor_sync(0xffffffffu, rs0, 2);
        rs1 += __shfl_xor_sync(0xffffffffu, rs1, 1);
        rs1 += __shfl_xor_sync(0xffffffffu, rs1, 2);
        if ((lane & 3) == 0) {
            redB[kh * 64 + rrow]     = rs0;
            redB[kh * 64 + rrow + 8] = rs1;
        }
        __syncthreads();   // B3
        rs0 += redB[(kh ^ 1) * 64 + rrow];
        rs1 += redB[(kh ^ 1) * 64 + rrow + 8];
        l0 = l0 * corr0 + rs0;
        l1 = l1 * corr1 + rs1;
        #pragma unroll
        for (int nt = 0; nt < 8; nt++) {
            o[nt][0] *= corr0; o[nt][1] *= corr0;
            o[nt][2] *= corr1; o[nt][3] *= corr1;
        }

        // ---- O += P @ V  (warp: its 32 KV rows, all 64 D cols) ----
        #pragma unroll
        for (int kt = 0; kt < 2; kt++) {
            uint32_t ph[4], pl[4];
            ph[0] = pack_hi(s[2*kt][0],   s[2*kt][1]);
            ph[1] = pack_hi(s[2*kt][2],   s[2*kt][3]);
            ph[2] = pack_hi(s[2*kt+1][0], s[2*kt+1][1]);
            ph[3] = pack_hi(s[2*kt+1][2], s[2*kt+1][3]);
            pl[0] = pack_lo(s[2*kt][0],   s[2*kt][1]);
            pl[1] = pack_lo(s[2*kt][2],   s[2*kt][3]);
            pl[2] = pack_lo(s[2*kt+1][0], s[2*kt+1][1]);
            pl[3] = pack_lo(s[2*kt+1][2], s[2*kt+1][3]);
            #pragma unroll
            for (int p = 0; p < 4; p++) {
                const int row = kh * 32 + kt * 16 + (g & 1) * 8 + l8;
                const int col = (2 * p + (g >> 1)) * 8;
                uint32_t vb[4], vl_[4];
                ldsm_x4_t(vb,  s2u(&sVh[row * LDB + col]));
                ldsm_x4_t(vl_, s2u(&sVl[row * LDB + col]));
                mma16816(o[2*p],   ph, vb);     mma16816(o[2*p],   ph, vl_);
                mma16816(o[2*p],   pl, vb);
                mma16816(o[2*p+1], ph, vb + 2); mma16816(o[2*p+1], ph, vl_ + 2);
                mma16816(o[2*p+1], pl, vb + 2);
            }
        }
        __syncthreads();   // B4: all reads of stage st done
    }

    // ---- combine the two KV-half partial O's, normalize, write ----
    float* Osm = (float*)ST;    // pipeline drained; reuse (64 x 66 floats)
    if (kh == 1) {
        #pragma unroll
        for (int nt = 0; nt < 8; nt++) {
            const int c = nt * 8 + (lane & 3) * 2;
            *(float2*)&Osm[rrow * 66 + c]       = make_float2(o[nt][0], o[nt][1]);
            *(float2*)&Osm[(rrow + 8) * 66 + c] = make_float2(o[nt][2], o[nt][3]);
        }
    }
    __syncthreads();
    if (kh == 0) {
        const float inv0 = 1.f / l0, inv1 = 1.f / l1;
        #pragma unroll
        for (int nt = 0; nt < 8; nt++) {
            const int c = nt * 8 + (lane & 3) * 2;
            const float2 a0 = *(float2*)&Osm[rrow * 66 + c];
            const float2 a1 = *(float2*)&Osm[(rrow + 8) * 66 + c];
            float2 o0 = make_float2((o[nt][0] + a0.x) * inv0, (o[nt][1] + a0.y) * inv0);
            float2 o1 = make_float2((o[nt][2] + a1.x) * inv1, (o[nt][3] + a1.y) * inv1);
            *(float2*)&out[((size_t)(n * LSEQ + q0 + rrow)) * D + c]     = o0;
            *(float2*)&out[((size_t)(n * LSEQ + q0 + rrow + 8)) * D + c] = o1;
        }
    }
}

// ---------------------------------------------------------------------------
// Launch
// ---------------------------------------------------------------------------
extern "C" void kernel_launch(void* const* d_in, const int* in_sizes, int n_in,
                              void* d_out, int out_size)
{
    const float* q  = (const float*)d_in[0];
    const float* k  = (const float*)d_in[1];
    const float* v  = (const float*)d_in[2];
    const float* Wq = (const float*)d_in[3];
    const float* bq = (const float*)d_in[4];
    const float* Wk = (const float*)d_in[5];
    const float* bk = (const float*)d_in[6];
    const float* Wv = (const float*)d_in[7];
    const float* bv = (const float*)d_in[8];
    float* out = (float*)d_out;

    const int smem_proj = 4 * 64 * LDB * 2;                       // 36864 B
    const int smem_attn = 10 * 64 * LDB * 2 + 256 * (int)sizeof(float);  // 93184 B
    cudaFuncSetAttribute(proj_mma, cudaFuncAttributeMaxDynamicSharedMemorySize, smem_proj);
    cudaFuncSetAttribute(attn_mma, cudaFuncAttributeMaxDynamicSharedMemorySize, smem_attn);

    proj_mma<<<dim3(MROWS / 64, 3), 128, smem_proj>>>(q, k, v, Wq, Wk, Wv, bq, bk, bv);
    attn_mma<<<dim3(LSEQ / 64, NB), 256, smem_attn>>>(out);
}